// round 3
// baseline (speedup 1.0000x reference)
#include <cuda_runtime.h>
#include <mma.h>
#include <cstdint>

using namespace nvcuda;

// Problem dims
#define BATCH 4096
#define TSTEPS 365
#define FDIM 16
#define HDIM 256
#define GDIM 1024          // 4*H
#define MT 32              // batch rows per CTA
#define NCTA (BATCH/MT)    // 128

// SMEM layout (in floats)
#define LDH 264            // h row stride (256 + 8 pad)
#define X_LD 24            // x row stride (16 + 8 pad)
#define W_LD 1032          // W chunk row stride (1024 + 8 pad)
#define SCR_LD 260         // gate scratch row stride (256 + 4 pad)

#define OFF_H    0
#define OFF_HE   (OFF_H + MT*LDH)            // 8448
#define OFF_X    (OFF_HE + MT*LDH)           // 16896
#define OFF_BIAS (OFF_X + MT*X_LD)           // 17664
#define OFF_WOUT (OFF_BIAS + 1024)           // 18688 (512 W_out + 2 b_out, padded)
#define OFF_WIH  (OFF_WOUT + 640)            // 19328
#define OFF_SH   (OFF_WIH + 16*W_LD)         // 35840 (shared region: W dbl-buf / scratch)
#define SMEM_FLOATS (OFF_SH + 16640)         // 52480 floats = 209920 B

// ---------------- device globals (preprocessed weights) ----------------
// g_WhhT[k][n'] : K-major, gate-interleaved perm (n' = j*4 + gate), tf32-rounded
__device__ float g_WhhT[256 * 1024];
__device__ float g_WihT[16 * 1024];
__device__ float g_biasP[1024];

__global__ void prep_kernel(const float* __restrict__ W_ih,
                            const float* __restrict__ W_hh,
                            const float* __restrict__ b_ih,
                            const float* __restrict__ b_hh) {
    int tid = blockIdx.x * blockDim.x + threadIdx.x;
    int stride = gridDim.x * blockDim.x;
    for (int o = tid; o < 256 * 1024; o += stride) {
        int k = o >> 10, np = o & 1023;
        int gate = np & 3, j = np >> 2;
        int n = gate * 256 + j;
        g_WhhT[o] = wmma::__float_to_tf32(W_hh[n * 256 + k]);
    }
    for (int o = tid; o < 16 * 1024; o += stride) {
        int k = o >> 10, np = o & 1023;
        int gate = np & 3, j = np >> 2;
        int n = gate * 256 + j;
        g_WihT[o] = wmma::__float_to_tf32(W_ih[n * 16 + k]);
    }
    for (int o = tid; o < 1024; o += stride) {
        int gate = o & 3, j = o >> 2;
        int n = gate * 256 + j;
        g_biasP[o] = b_ih[n] + b_hh[n];
    }
}

// ---------------- helpers ----------------
__device__ __forceinline__ void cp_async16(float* smem_dst, const float* gsrc) {
    unsigned saddr = (unsigned)__cvta_generic_to_shared(smem_dst);
    asm volatile("cp.async.cg.shared.global [%0], [%1], 16;\n" :: "r"(saddr), "l"(gsrc));
}
__device__ __forceinline__ void cp_commit() {
    asm volatile("cp.async.commit_group;\n");
}
__device__ __forceinline__ void cp_wait0() {
    asm volatile("cp.async.wait_group 0;\n");
}

__device__ __forceinline__ float sigf(float x) {
    x = fminf(fmaxf(x, -30.f), 30.f);
    float e = __expf(-x);
    return __fdividef(1.f, 1.f + e);
}
__device__ __forceinline__ float tanhf_fast(float x) {
    x = fminf(fmaxf(x, -15.f), 15.f);
    float e = __expf(-2.f * x);
    return __fdividef(1.f - e, 1.f + e);
}

// ---------------- main persistent LSTM kernel ----------------
__global__ void __launch_bounds__(256, 1)
lstm_kernel(const float* __restrict__ w,
            const float* __restrict__ W_out,
            const float* __restrict__ b_out,
            float* __restrict__ out) {
    extern __shared__ float sm[];
    float* h_tf   = sm + OFF_H;     // tf32-rounded h (mma operand)
    float* h_ex   = sm + OFF_HE;    // exact fp32 h (for head / output)
    float* x_sm   = sm + OFF_X;
    float* bias_sm= sm + OFF_BIAS;
    float* wout_sm= sm + OFF_WOUT;  // [0..511] W_out, [512..513] b_out
    float* wih_sm = sm + OFF_WIH;   // [16][W_LD]
    float* shreg  = sm + OFF_SH;    // W double-buffer / gate scratch (aliased)

    const int tid = threadIdx.x;
    const int wp  = tid >> 5;
    const int ln  = tid & 31;
    const int b0  = blockIdx.x * MT;

    // init: zero h, load bias/W_out/W_ih
    for (int i = tid; i < MT * LDH; i += 256) { h_tf[i] = 0.f; h_ex[i] = 0.f; }
    for (int i = tid; i < 1024; i += 256) bias_sm[i] = g_biasP[i];
    for (int i = tid; i < 512; i += 256) wout_sm[i] = W_out[i];
    if (tid < 2) wout_sm[512 + tid] = b_out[tid];
    for (int i = tid; i < 16 * 1024; i += 256) {
        int k = i >> 10, n = i & 1023;
        wih_sm[k * W_LD + n] = g_WihT[i];
    }
    __syncthreads();

    // cell state in registers: lane owns 4 rows x 8 cols of its warp's region
    float creg[32];
#pragma unroll
    for (int i = 0; i < 32; i++) creg[i] = 0.f;

    const int tr   = wp & 1;          // tile-row: rows [tr*16, tr*16+16)
    const int cg   = wp >> 1;         // col group: perm cols [cg*256, cg*256+256)
    const int cb   = cg * 256;
    const int slot = cg;              // scratch slot
    const int phase= wp & 1;

    wmma::fragment<wmma::accumulator, 16, 16, 8, float> acc[16];

    for (int t = 0; t < TSTEPS; ++t) {
        // stage x_t (tf32-rounded)
        for (int i = tid; i < MT * FDIM; i += 256) {
            int r = i >> 4, f = i & 15;
            x_sm[r * X_LD + f] =
                wmma::__float_to_tf32(w[((size_t)(b0 + r) * TSTEPS + t) * FDIM + f]);
        }
        // stage W_hh chunk 0 into buf 0
#pragma unroll
        for (int it = 0; it < 8; ++it) {
            int lin = it * 256 + tid;
            int kr = lin >> 8, c4 = lin & 255;
            cp_async16(&shreg[kr * W_LD + c4 * 4], &g_WhhT[kr * 1024 + c4 * 4]);
        }
        cp_commit();
        cp_wait0();
        __syncthreads();

#pragma unroll
        for (int i = 0; i < 16; i++) wmma::fill_fragment(acc[i], 0.f);

        // x @ W_ih^T : K=16 (2 k-steps)
#pragma unroll
        for (int ks = 0; ks < 2; ++ks) {
            wmma::fragment<wmma::matrix_a, 16, 16, 8, wmma::precision::tf32, wmma::row_major> a;
            wmma::load_matrix_sync(a, x_sm + tr * 16 * X_LD + ks * 8, X_LD);
#pragma unroll
            for (int i = 0; i < 16; i++) {
                wmma::fragment<wmma::matrix_b, 16, 16, 8, wmma::precision::tf32, wmma::row_major> bfr;
                wmma::load_matrix_sync(bfr, wih_sm + ks * 8 * W_LD + cb + i * 16, W_LD);
                wmma::mma_sync(acc[i], a, bfr, acc[i]);
            }
        }

        // h @ W_hh^T : K=256, 32 chunks of 8, double-buffered cp.async
        for (int kc = 0; kc < 32; ++kc) {
            float* cur = shreg + (kc & 1) * 8256;
            if (kc < 31) {
                float* nxt = shreg + ((kc + 1) & 1) * 8256;
#pragma unroll
                for (int it = 0; it < 8; ++it) {
                    int lin = it * 256 + tid;
                    int kr = lin >> 8, c4 = lin & 255;
                    cp_async16(&nxt[kr * W_LD + c4 * 4],
                               &g_WhhT[((kc + 1) * 8 + kr) * 1024 + c4 * 4]);
                }
                cp_commit();
            }
            wmma::fragment<wmma::matrix_a, 16, 16, 8, wmma::precision::tf32, wmma::row_major> a;
            wmma::load_matrix_sync(a, h_tf + tr * 16 * LDH + kc * 8, LDH);
#pragma unroll
            for (int i = 0; i < 16; i++) {
                wmma::fragment<wmma::matrix_b, 16, 16, 8, wmma::precision::tf32, wmma::row_major> bfr;
                wmma::load_matrix_sync(bfr, cur + cb + i * 16, W_LD);
                wmma::mma_sync(acc[i], a, bfr, acc[i]);
            }
            if (kc < 31) cp_wait0();
            __syncthreads();  // buffer reuse barrier (and last-iter: scratch-alias barrier)
        }

        // epilogue: two phases share 4 scratch slots (aliased over W buffers)
        for (int ph = 0; ph < 2; ++ph) {
            if (phase == ph) {
                float* scr = shreg + slot * 4160;
#pragma unroll
                for (int i = 0; i < 16; i++)
                    wmma::store_matrix_sync(scr + i * 16, acc[i], SCR_LD, wmma::mem_row_major);
            }
            __syncthreads();
            if (phase == ph) {
                float* scr = shreg + slot * 4160;
                const int rbase = (ln >> 3) * 4;
                const int jbase = (ln & 7) * 8;
#pragma unroll
                for (int rr = 0; rr < 4; ++rr) {
                    const int r = rbase + rr;
                    const int rowg = tr * 16 + r;
#pragma unroll
                    for (int jj = 0; jj < 8; ++jj) {
                        const int jl = jbase + jj;
                        const int jg = cg * 64 + jl;
                        float4 gv = *reinterpret_cast<float4*>(scr + r * SCR_LD + jl * 4);
                        float4 bv = *reinterpret_cast<const float4*>(bias_sm + jg * 4);
                        float gi = sigf(gv.x + bv.x);
                        float gf = sigf(gv.y + bv.y);
                        float gg = tanhf_fast(gv.z + bv.z);
                        float go = sigf(gv.w + bv.w);
                        const int ci = rr * 8 + jj;
                        float c = gf * creg[ci] + gi * gg;
                        creg[ci] = c;
                        float hn = go * tanhf_fast(c);
                        h_ex[rowg * LDH + jg] = hn;
                        h_tf[rowg * LDH + jg] = wmma::__float_to_tf32(hn);
                        if (t == TSTEPS - 1)
                            out[8192 + (size_t)(b0 + rowg) * 256 + jg] = hn;
                    }
                }
            }
            __syncthreads();
        }
    }

    // head: tz0 = ELU(h) @ W_out^T + b_out  (exact fp32)
    if (tid < 64) {
        const int r = tid >> 1, oi = tid & 1;
        float s = wout_sm[512 + oi];
        for (int j = 0; j < 256; ++j) {
            float v = h_ex[r * LDH + j];
            float e = (v > 0.f) ? v : (__expf(v) - 1.f);
            s += e * wout_sm[oi * 256 + j];
        }
        out[(size_t)oi * 4096 + (b0 + r)] = s;
    }
}

// ---------------- launch ----------------
extern "C" void kernel_launch(void* const* d_in, const int* in_sizes, int n_in,
                              void* d_out, int out_size) {
    const float* w     = (const float*)d_in[0];
    const float* W_ih  = (const float*)d_in[1];
    const float* W_hh  = (const float*)d_in[2];
    const float* b_ih  = (const float*)d_in[3];
    const float* b_hh  = (const float*)d_in[4];
    const float* W_out = (const float*)d_in[5];
    const float* b_out = (const float*)d_in[6];
    float* out = (float*)d_out;

    prep_kernel<<<256, 256>>>(W_ih, W_hh, b_ih, b_hh);

    const int smem_bytes = SMEM_FLOATS * sizeof(float);  // 209920 B
    cudaFuncSetAttribute(lstm_kernel, cudaFuncAttributeMaxDynamicSharedMemorySize, smem_bytes);
    lstm_kernel<<<NCTA, 256, smem_bytes>>>(w, W_out, b_out, out);
}

// round 4
// speedup vs baseline: 1.0002x; 1.0002x over previous
#include <cuda_runtime.h>
#include <mma.h>
#include <cstdint>

using namespace nvcuda;

// Problem dims
#define BATCH 4096
#define TSTEPS 365
#define FDIM 16
#define HDIM 256
#define GDIM 1024          // 4*H
#define MT 32              // batch rows per CTA
#define NCTA (BATCH/MT)    // 128

// SMEM layout (in floats)
#define LDH 264            // h row stride (256 + 8 pad)
#define X_LD 24            // x row stride (16 + 8 pad)
#define W_LD 1032          // W chunk row stride (1024 + 8 pad)
#define SCR_LD 260         // gate scratch row stride (256 + 4 pad)

#define OFF_H    0
#define OFF_HE   (OFF_H + MT*LDH)            // 8448
#define OFF_X    (OFF_HE + MT*LDH)           // 16896
#define OFF_BIAS (OFF_X + MT*X_LD)           // 17664
#define OFF_WOUT (OFF_BIAS + 1024)           // 18688 (512 W_out + 2 b_out, padded)
#define OFF_WIH  (OFF_WOUT + 640)            // 19328
#define OFF_SH   (OFF_WIH + 16*W_LD)         // 35840 (shared region: W dbl-buf / scratch)
#define SMEM_FLOATS (OFF_SH + 16640)         // 52480 floats = 209920 B

// ---------------- device globals (preprocessed weights) ----------------
// g_WhhT[k][n'] : K-major, gate-interleaved perm (n' = j*4 + gate), tf32-rounded
__device__ float g_WhhT[256 * 1024];
__device__ float g_WihT[16 * 1024];
__device__ float g_biasP[1024];

__global__ void prep_kernel(const float* __restrict__ W_ih,
                            const float* __restrict__ W_hh,
                            const float* __restrict__ b_ih,
                            const float* __restrict__ b_hh) {
    int tid = blockIdx.x * blockDim.x + threadIdx.x;
    int stride = gridDim.x * blockDim.x;
    for (int o = tid; o < 256 * 1024; o += stride) {
        int k = o >> 10, np = o & 1023;
        int gate = np & 3, j = np >> 2;
        int n = gate * 256 + j;
        g_WhhT[o] = wmma::__float_to_tf32(W_hh[n * 256 + k]);
    }
    for (int o = tid; o < 16 * 1024; o += stride) {
        int k = o >> 10, np = o & 1023;
        int gate = np & 3, j = np >> 2;
        int n = gate * 256 + j;
        g_WihT[o] = wmma::__float_to_tf32(W_ih[n * 16 + k]);
    }
    for (int o = tid; o < 1024; o += stride) {
        int gate = o & 3, j = o >> 2;
        int n = gate * 256 + j;
        g_biasP[o] = b_ih[n] + b_hh[n];
    }
}

// ---------------- helpers ----------------
__device__ __forceinline__ void cp_async16(float* smem_dst, const float* gsrc) {
    unsigned saddr = (unsigned)__cvta_generic_to_shared(smem_dst);
    asm volatile("cp.async.cg.shared.global [%0], [%1], 16;\n" :: "r"(saddr), "l"(gsrc));
}
__device__ __forceinline__ void cp_commit() {
    asm volatile("cp.async.commit_group;\n");
}
__device__ __forceinline__ void cp_wait0() {
    asm volatile("cp.async.wait_group 0;\n");
}

__device__ __forceinline__ float sigf(float x) {
    x = fminf(fmaxf(x, -30.f), 30.f);
    float e = __expf(-x);
    return __fdividef(1.f, 1.f + e);
}
__device__ __forceinline__ float tanhf_fast(float x) {
    x = fminf(fmaxf(x, -15.f), 15.f);
    float e = __expf(-2.f * x);
    return __fdividef(1.f - e, 1.f + e);
}

// ---------------- main persistent LSTM kernel ----------------
__global__ void __launch_bounds__(256, 1)
lstm_kernel(const float* __restrict__ w,
            const float* __restrict__ W_out,
            const float* __restrict__ b_out,
            float* __restrict__ out) {
    extern __shared__ float sm[];
    float* h_tf   = sm + OFF_H;     // tf32-rounded h (mma operand)
    float* h_ex   = sm + OFF_HE;    // exact fp32 h (for head / output)
    float* x_sm   = sm + OFF_X;
    float* bias_sm= sm + OFF_BIAS;
    float* wout_sm= sm + OFF_WOUT;  // [0..511] W_out, [512..513] b_out
    float* wih_sm = sm + OFF_WIH;   // [16][W_LD]
    float* shreg  = sm + OFF_SH;    // W double-buffer / gate scratch (aliased)

    const int tid = threadIdx.x;
    const int wp  = tid >> 5;
    const int ln  = tid & 31;
    const int b0  = blockIdx.x * MT;

    // init: zero h, load bias/W_out/W_ih
    for (int i = tid; i < MT * LDH; i += 256) { h_tf[i] = 0.f; h_ex[i] = 0.f; }
    for (int i = tid; i < 1024; i += 256) bias_sm[i] = g_biasP[i];
    for (int i = tid; i < 512; i += 256) wout_sm[i] = W_out[i];
    if (tid < 2) wout_sm[512 + tid] = b_out[tid];
    for (int i = tid; i < 16 * 1024; i += 256) {
        int k = i >> 10, n = i & 1023;
        wih_sm[k * W_LD + n] = g_WihT[i];
    }
    __syncthreads();

    // cell state in registers: lane owns 4 rows x 8 cols of its warp's region
    float creg[32];
#pragma unroll
    for (int i = 0; i < 32; i++) creg[i] = 0.f;

    const int tr   = wp & 1;          // tile-row: rows [tr*16, tr*16+16)
    const int cg   = wp >> 1;         // col group: perm cols [cg*256, cg*256+256)
    const int cb   = cg * 256;
    const int slot = cg;              // scratch slot
    const int phase= wp & 1;

    wmma::fragment<wmma::accumulator, 16, 16, 8, float> acc[16];

    for (int t = 0; t < TSTEPS; ++t) {
        // stage x_t (tf32-rounded)
        for (int i = tid; i < MT * FDIM; i += 256) {
            int r = i >> 4, f = i & 15;
            x_sm[r * X_LD + f] =
                wmma::__float_to_tf32(w[((size_t)(b0 + r) * TSTEPS + t) * FDIM + f]);
        }
        // stage W_hh chunk 0 into buf 0
#pragma unroll
        for (int it = 0; it < 8; ++it) {
            int lin = it * 256 + tid;
            int kr = lin >> 8, c4 = lin & 255;
            cp_async16(&shreg[kr * W_LD + c4 * 4], &g_WhhT[kr * 1024 + c4 * 4]);
        }
        cp_commit();
        cp_wait0();
        __syncthreads();

#pragma unroll
        for (int i = 0; i < 16; i++) wmma::fill_fragment(acc[i], 0.f);

        // x @ W_ih^T : K=16 (2 k-steps)
#pragma unroll
        for (int ks = 0; ks < 2; ++ks) {
            wmma::fragment<wmma::matrix_a, 16, 16, 8, wmma::precision::tf32, wmma::row_major> a;
            wmma::load_matrix_sync(a, x_sm + tr * 16 * X_LD + ks * 8, X_LD);
#pragma unroll
            for (int i = 0; i < 16; i++) {
                wmma::fragment<wmma::matrix_b, 16, 16, 8, wmma::precision::tf32, wmma::row_major> bfr;
                wmma::load_matrix_sync(bfr, wih_sm + ks * 8 * W_LD + cb + i * 16, W_LD);
                wmma::mma_sync(acc[i], a, bfr, acc[i]);
            }
        }

        // h @ W_hh^T : K=256, 32 chunks of 8, double-buffered cp.async
        for (int kc = 0; kc < 32; ++kc) {
            float* cur = shreg + (kc & 1) * 8256;
            if (kc < 31) {
                float* nxt = shreg + ((kc + 1) & 1) * 8256;
#pragma unroll
                for (int it = 0; it < 8; ++it) {
                    int lin = it * 256 + tid;
                    int kr = lin >> 8, c4 = lin & 255;
                    cp_async16(&nxt[kr * W_LD + c4 * 4],
                               &g_WhhT[((kc + 1) * 8 + kr) * 1024 + c4 * 4]);
                }
                cp_commit();
            }
            wmma::fragment<wmma::matrix_a, 16, 16, 8, wmma::precision::tf32, wmma::row_major> a;
            wmma::load_matrix_sync(a, h_tf + tr * 16 * LDH + kc * 8, LDH);
#pragma unroll
            for (int i = 0; i < 16; i++) {
                wmma::fragment<wmma::matrix_b, 16, 16, 8, wmma::precision::tf32, wmma::row_major> bfr;
                wmma::load_matrix_sync(bfr, cur + cb + i * 16, W_LD);
                wmma::mma_sync(acc[i], a, bfr, acc[i]);
            }
            if (kc < 31) cp_wait0();
            __syncthreads();  // buffer reuse barrier (and last-iter: scratch-alias barrier)
        }

        // epilogue: two phases share 4 scratch slots (aliased over W buffers)
        for (int ph = 0; ph < 2; ++ph) {
            if (phase == ph) {
                float* scr = shreg + slot * 4160;
#pragma unroll
                for (int i = 0; i < 16; i++)
                    wmma::store_matrix_sync(scr + i * 16, acc[i], SCR_LD, wmma::mem_row_major);
            }
            __syncthreads();
            if (phase == ph) {
                float* scr = shreg + slot * 4160;
                const int rbase = (ln >> 3) * 4;
                const int jbase = (ln & 7) * 8;
#pragma unroll
                for (int rr = 0; rr < 4; ++rr) {
                    const int r = rbase + rr;
                    const int rowg = tr * 16 + r;
#pragma unroll
                    for (int jj = 0; jj < 8; ++jj) {
                        const int jl = jbase + jj;
                        const int jg = cg * 64 + jl;
                        float4 gv = *reinterpret_cast<float4*>(scr + r * SCR_LD + jl * 4);
                        float4 bv = *reinterpret_cast<const float4*>(bias_sm + jg * 4);
                        float gi = sigf(gv.x + bv.x);
                        float gf = sigf(gv.y + bv.y);
                        float gg = tanhf_fast(gv.z + bv.z);
                        float go = sigf(gv.w + bv.w);
                        const int ci = rr * 8 + jj;
                        float c = gf * creg[ci] + gi * gg;
                        creg[ci] = c;
                        float hn = go * tanhf_fast(c);
                        h_ex[rowg * LDH + jg] = hn;
                        h_tf[rowg * LDH + jg] = wmma::__float_to_tf32(hn);
                        if (t == TSTEPS - 1)
                            out[8192 + (size_t)(b0 + rowg) * 256 + jg] = hn;
                    }
                }
            }
            __syncthreads();
        }
    }

    // head: tz0 = ELU(h) @ W_out^T + b_out  (exact fp32)
    if (tid < 64) {
        const int r = tid >> 1, oi = tid & 1;
        float s = wout_sm[512 + oi];
        for (int j = 0; j < 256; ++j) {
            float v = h_ex[r * LDH + j];
            float e = (v > 0.f) ? v : (__expf(v) - 1.f);
            s += e * wout_sm[oi * 256 + j];
        }
        out[(size_t)oi * 4096 + (b0 + r)] = s;
    }
}

// ---------------- launch ----------------
extern "C" void kernel_launch(void* const* d_in, const int* in_sizes, int n_in,
                              void* d_out, int out_size) {
    const float* w     = (const float*)d_in[0];
    const float* W_ih  = (const float*)d_in[1];
    const float* W_hh  = (const float*)d_in[2];
    const float* b_ih  = (const float*)d_in[3];
    const float* b_hh  = (const float*)d_in[4];
    const float* W_out = (const float*)d_in[5];
    const float* b_out = (const float*)d_in[6];
    float* out = (float*)d_out;

    prep_kernel<<<256, 256>>>(W_ih, W_hh, b_ih, b_hh);

    const int smem_bytes = SMEM_FLOATS * sizeof(float);  // 209920 B
    cudaFuncSetAttribute(lstm_kernel, cudaFuncAttributeMaxDynamicSharedMemorySize, smem_bytes);
    lstm_kernel<<<NCTA, 256, smem_bytes>>>(w, W_out, b_out, out);
}

// round 5
// speedup vs baseline: 1.0018x; 1.0016x over previous
#include <cuda_runtime.h>
#include <mma.h>
#include <cstdint>

using namespace nvcuda;

// Problem dims
#define BATCH 4096
#define TSTEPS 365
#define FDIM 16
#define HDIM 256
#define GDIM 1024          // 4*H
#define MT 32              // batch rows per CTA
#define NCTA (BATCH/MT)    // 128

// SMEM layout (in floats)
#define LDH 264            // h row stride (256 + 8 pad)
#define X_LD 24            // x row stride (16 + 8 pad)
#define W_LD 1032          // W chunk row stride (1024 + 8 pad)
#define SCR_LD 260         // gate scratch row stride (256 + 4 pad)

#define OFF_H    0
#define OFF_HE   (OFF_H + MT*LDH)            // 8448
#define OFF_X    (OFF_HE + MT*LDH)           // 16896
#define OFF_BIAS (OFF_X + MT*X_LD)           // 17664
#define OFF_WOUT (OFF_BIAS + 1024)           // 18688 (512 W_out + 2 b_out, padded)
#define OFF_WIH  (OFF_WOUT + 640)            // 19328
#define OFF_SH   (OFF_WIH + 16*W_LD)         // 35840 (shared region: W dbl-buf / scratch)
#define SMEM_FLOATS (OFF_SH + 16640)         // 52480 floats = 209920 B

// ---------------- device globals (preprocessed weights) ----------------
// g_WhhT[k][n'] : K-major, gate-interleaved perm (n' = j*4 + gate), tf32-rounded
__device__ float g_WhhT[256 * 1024];
__device__ float g_WihT[16 * 1024];
__device__ float g_biasP[1024];

__global__ void prep_kernel(const float* __restrict__ W_ih,
                            const float* __restrict__ W_hh,
                            const float* __restrict__ b_ih,
                            const float* __restrict__ b_hh) {
    int tid = blockIdx.x * blockDim.x + threadIdx.x;
    int stride = gridDim.x * blockDim.x;
    for (int o = tid; o < 256 * 1024; o += stride) {
        int k = o >> 10, np = o & 1023;
        int gate = np & 3, j = np >> 2;
        int n = gate * 256 + j;
        g_WhhT[o] = wmma::__float_to_tf32(W_hh[n * 256 + k]);
    }
    for (int o = tid; o < 16 * 1024; o += stride) {
        int k = o >> 10, np = o & 1023;
        int gate = np & 3, j = np >> 2;
        int n = gate * 256 + j;
        g_WihT[o] = wmma::__float_to_tf32(W_ih[n * 16 + k]);
    }
    for (int o = tid; o < 1024; o += stride) {
        int gate = o & 3, j = o >> 2;
        int n = gate * 256 + j;
        g_biasP[o] = b_ih[n] + b_hh[n];
    }
}

// ---------------- helpers ----------------
__device__ __forceinline__ void cp_async16(float* smem_dst, const float* gsrc) {
    unsigned saddr = (unsigned)__cvta_generic_to_shared(smem_dst);
    asm volatile("cp.async.cg.shared.global [%0], [%1], 16;\n" :: "r"(saddr), "l"(gsrc));
}
__device__ __forceinline__ void cp_commit() {
    asm volatile("cp.async.commit_group;\n");
}
__device__ __forceinline__ void cp_wait0() {
    asm volatile("cp.async.wait_group 0;\n");
}

__device__ __forceinline__ float sigf(float x) {
    x = fminf(fmaxf(x, -30.f), 30.f);
    float e = __expf(-x);
    return __fdividef(1.f, 1.f + e);
}
__device__ __forceinline__ float tanhf_fast(float x) {
    x = fminf(fmaxf(x, -15.f), 15.f);
    float e = __expf(-2.f * x);
    return __fdividef(1.f - e, 1.f + e);
}

// ---------------- main persistent LSTM kernel ----------------
__global__ void __launch_bounds__(256, 1)
lstm_kernel(const float* __restrict__ w,
            const float* __restrict__ W_out,
            const float* __restrict__ b_out,
            float* __restrict__ out) {
    extern __shared__ float sm[];
    float* h_tf   = sm + OFF_H;     // tf32-rounded h (mma operand)
    float* h_ex   = sm + OFF_HE;    // exact fp32 h (for head / output)
    float* x_sm   = sm + OFF_X;
    float* bias_sm= sm + OFF_BIAS;
    float* wout_sm= sm + OFF_WOUT;  // [0..511] W_out, [512..513] b_out
    float* wih_sm = sm + OFF_WIH;   // [16][W_LD]
    float* shreg  = sm + OFF_SH;    // W double-buffer / gate scratch (aliased)

    const int tid = threadIdx.x;
    const int wp  = tid >> 5;
    const int ln  = tid & 31;
    const int b0  = blockIdx.x * MT;

    // init: zero h, load bias/W_out/W_ih
    for (int i = tid; i < MT * LDH; i += 256) { h_tf[i] = 0.f; h_ex[i] = 0.f; }
    for (int i = tid; i < 1024; i += 256) bias_sm[i] = g_biasP[i];
    for (int i = tid; i < 512; i += 256) wout_sm[i] = W_out[i];
    if (tid < 2) wout_sm[512 + tid] = b_out[tid];
    for (int i = tid; i < 16 * 1024; i += 256) {
        int k = i >> 10, n = i & 1023;
        wih_sm[k * W_LD + n] = g_WihT[i];
    }
    __syncthreads();

    // cell state in registers: lane owns 4 rows x 8 cols of its warp's region
    float creg[32];
#pragma unroll
    for (int i = 0; i < 32; i++) creg[i] = 0.f;

    const int tr   = wp & 1;          // tile-row: rows [tr*16, tr*16+16)
    const int cg   = wp >> 1;         // col group: perm cols [cg*256, cg*256+256)
    const int cb   = cg * 256;
    const int slot = cg;              // scratch slot
    const int phase= wp & 1;

    wmma::fragment<wmma::accumulator, 16, 16, 8, float> acc[16];

    for (int t = 0; t < TSTEPS; ++t) {
        // stage x_t (tf32-rounded)
        for (int i = tid; i < MT * FDIM; i += 256) {
            int r = i >> 4, f = i & 15;
            x_sm[r * X_LD + f] =
                wmma::__float_to_tf32(w[((size_t)(b0 + r) * TSTEPS + t) * FDIM + f]);
        }
        // stage W_hh chunk 0 into buf 0
#pragma unroll
        for (int it = 0; it < 8; ++it) {
            int lin = it * 256 + tid;
            int kr = lin >> 8, c4 = lin & 255;
            cp_async16(&shreg[kr * W_LD + c4 * 4], &g_WhhT[kr * 1024 + c4 * 4]);
        }
        cp_commit();
        cp_wait0();
        __syncthreads();

#pragma unroll
        for (int i = 0; i < 16; i++) wmma::fill_fragment(acc[i], 0.f);

        // x @ W_ih^T : K=16 (2 k-steps)
#pragma unroll
        for (int ks = 0; ks < 2; ++ks) {
            wmma::fragment<wmma::matrix_a, 16, 16, 8, wmma::precision::tf32, wmma::row_major> a;
            wmma::load_matrix_sync(a, x_sm + tr * 16 * X_LD + ks * 8, X_LD);
#pragma unroll
            for (int i = 0; i < 16; i++) {
                wmma::fragment<wmma::matrix_b, 16, 16, 8, wmma::precision::tf32, wmma::row_major> bfr;
                wmma::load_matrix_sync(bfr, wih_sm + ks * 8 * W_LD + cb + i * 16, W_LD);
                wmma::mma_sync(acc[i], a, bfr, acc[i]);
            }
        }

        // h @ W_hh^T : K=256, 32 chunks of 8, double-buffered cp.async
        for (int kc = 0; kc < 32; ++kc) {
            float* cur = shreg + (kc & 1) * 8256;
            if (kc < 31) {
                float* nxt = shreg + ((kc + 1) & 1) * 8256;
#pragma unroll
                for (int it = 0; it < 8; ++it) {
                    int lin = it * 256 + tid;
                    int kr = lin >> 8, c4 = lin & 255;
                    cp_async16(&nxt[kr * W_LD + c4 * 4],
                               &g_WhhT[((kc + 1) * 8 + kr) * 1024 + c4 * 4]);
                }
                cp_commit();
            }
            wmma::fragment<wmma::matrix_a, 16, 16, 8, wmma::precision::tf32, wmma::row_major> a;
            wmma::load_matrix_sync(a, h_tf + tr * 16 * LDH + kc * 8, LDH);
#pragma unroll
            for (int i = 0; i < 16; i++) {
                wmma::fragment<wmma::matrix_b, 16, 16, 8, wmma::precision::tf32, wmma::row_major> bfr;
                wmma::load_matrix_sync(bfr, cur + cb + i * 16, W_LD);
                wmma::mma_sync(acc[i], a, bfr, acc[i]);
            }
            if (kc < 31) cp_wait0();
            __syncthreads();  // buffer reuse barrier (and last-iter: scratch-alias barrier)
        }

        // epilogue: two phases share 4 scratch slots (aliased over W buffers)
        for (int ph = 0; ph < 2; ++ph) {
            if (phase == ph) {
                float* scr = shreg + slot * 4160;
#pragma unroll
                for (int i = 0; i < 16; i++)
                    wmma::store_matrix_sync(scr + i * 16, acc[i], SCR_LD, wmma::mem_row_major);
            }
            __syncthreads();
            if (phase == ph) {
                float* scr = shreg + slot * 4160;
                const int rbase = (ln >> 3) * 4;
                const int jbase = (ln & 7) * 8;
#pragma unroll
                for (int rr = 0; rr < 4; ++rr) {
                    const int r = rbase + rr;
                    const int rowg = tr * 16 + r;
#pragma unroll
                    for (int jj = 0; jj < 8; ++jj) {
                        const int jl = jbase + jj;
                        const int jg = cg * 64 + jl;
                        float4 gv = *reinterpret_cast<float4*>(scr + r * SCR_LD + jl * 4);
                        float4 bv = *reinterpret_cast<const float4*>(bias_sm + jg * 4);
                        float gi = sigf(gv.x + bv.x);
                        float gf = sigf(gv.y + bv.y);
                        float gg = tanhf_fast(gv.z + bv.z);
                        float go = sigf(gv.w + bv.w);
                        const int ci = rr * 8 + jj;
                        float c = gf * creg[ci] + gi * gg;
                        creg[ci] = c;
                        float hn = go * tanhf_fast(c);
                        h_ex[rowg * LDH + jg] = hn;
                        h_tf[rowg * LDH + jg] = wmma::__float_to_tf32(hn);
                        if (t == TSTEPS - 1)
                            out[8192 + (size_t)(b0 + rowg) * 256 + jg] = hn;
                    }
                }
            }
            __syncthreads();
        }
    }

    // head: tz0 = ELU(h) @ W_out^T + b_out  (exact fp32)
    if (tid < 64) {
        const int r = tid >> 1, oi = tid & 1;
        float s = wout_sm[512 + oi];
        for (int j = 0; j < 256; ++j) {
            float v = h_ex[r * LDH + j];
            float e = (v > 0.f) ? v : (__expf(v) - 1.f);
            s += e * wout_sm[oi * 256 + j];
        }
        out[(size_t)oi * 4096 + (b0 + r)] = s;
    }
}

// ---------------- launch ----------------
extern "C" void kernel_launch(void* const* d_in, const int* in_sizes, int n_in,
                              void* d_out, int out_size) {
    const float* w     = (const float*)d_in[0];
    const float* W_ih  = (const float*)d_in[1];
    const float* W_hh  = (const float*)d_in[2];
    const float* b_ih  = (const float*)d_in[3];
    const float* b_hh  = (const float*)d_in[4];
    const float* W_out = (const float*)d_in[5];
    const float* b_out = (const float*)d_in[6];
    float* out = (float*)d_out;

    prep_kernel<<<256, 256>>>(W_ih, W_hh, b_ih, b_hh);

    const int smem_bytes = SMEM_FLOATS * sizeof(float);  // 209920 B
    cudaFuncSetAttribute(lstm_kernel, cudaFuncAttributeMaxDynamicSharedMemorySize, smem_bytes);
    lstm_kernel<<<NCTA, 256, smem_bytes>>>(w, W_out, b_out, out);
}

// round 6
// speedup vs baseline: 1.4081x; 1.4056x over previous
#include <cuda_runtime.h>
#include <mma.h>
#include <cstdint>

using namespace nvcuda;

// Problem dims
#define BATCH 4096
#define TSTEPS 365
#define FDIM 16
#define MT 32              // batch rows per CTA
#define NCTA (BATCH/MT)    // 128

// SMEM layout (in floats)
#define LDH 264            // h row stride (256 + 8 pad)
#define X_LD 24            // x row stride
#define W_LD 1032          // W_ih smem row stride
#define WB_LD 132          // per-warp W chunk row stride (128 + 4 pad)
#define SCR_LD 132         // gate scratch row stride

#define OFF_H    0
#define OFF_HE   (OFF_H + MT*LDH)            // 8448
#define OFF_X    (OFF_HE + MT*LDH)           // 16896
#define OFF_BIAS (OFF_X + MT*X_LD)           // 17664
#define OFF_WOUT (OFF_BIAS + 1024)           // 18688
#define OFF_WIH  (OFF_WOUT + 640)            // 19328
#define OFF_SH   (OFF_WIH + 16*W_LD)         // 35840 (per-warp W dbl-buf / scratch, aliased)
#define SMEM_FLOATS (OFF_SH + 16896)         // 52736 floats = 210944 B

// ---------------- device globals (preprocessed weights) ----------------
// g_WhhT[k][n'] : K-major, gate-interleaved perm (n' = j*4 + gate), tf32-rounded
__device__ float g_WhhT[256 * 1024];
__device__ float g_WihT[16 * 1024];
__device__ float g_biasP[1024];

__global__ void prep_kernel(const float* __restrict__ W_ih,
                            const float* __restrict__ W_hh,
                            const float* __restrict__ b_ih,
                            const float* __restrict__ b_hh) {
    int tid = blockIdx.x * blockDim.x + threadIdx.x;
    int stride = gridDim.x * blockDim.x;
    for (int o = tid; o < 256 * 1024; o += stride) {
        int k = o >> 10, np = o & 1023;
        int gate = np & 3, j = np >> 2;
        int n = gate * 256 + j;
        g_WhhT[o] = wmma::__float_to_tf32(W_hh[n * 256 + k]);
    }
    for (int o = tid; o < 16 * 1024; o += stride) {
        int k = o >> 10, np = o & 1023;
        int gate = np & 3, j = np >> 2;
        int n = gate * 256 + j;
        g_WihT[o] = wmma::__float_to_tf32(W_ih[n * 16 + k]);
    }
    for (int o = tid; o < 1024; o += stride) {
        int gate = o & 3, j = o >> 2;
        int n = gate * 256 + j;
        g_biasP[o] = b_ih[n] + b_hh[n];
    }
}

// ---------------- helpers ----------------
__device__ __forceinline__ void cp_async16(float* smem_dst, const float* gsrc) {
    unsigned saddr = (unsigned)__cvta_generic_to_shared(smem_dst);
    asm volatile("cp.async.cg.shared.global [%0], [%1], 16;\n" :: "r"(saddr), "l"(gsrc));
}
__device__ __forceinline__ void cp_commit() {
    asm volatile("cp.async.commit_group;\n");
}
__device__ __forceinline__ void cp_wait0() {
    asm volatile("cp.async.wait_group 0;\n");
}
__device__ __forceinline__ void cp_wait1() {
    asm volatile("cp.async.wait_group 1;\n");
}

// sigmoid via HW tanh: 1 MUFU + 2 FMA, abs err ~2.4e-4
__device__ __forceinline__ float sig_approx(float x) {
    float t;
    asm("tanh.approx.f32 %0, %1;" : "=f"(t) : "f"(0.5f * x));
    return fmaf(0.5f, t, 0.5f);
}
// accurate-ish tanh (EX2 + RCP): used where error feeds the output directly
__device__ __forceinline__ float tanhf_fast(float x) {
    x = fminf(fmaxf(x, -15.f), 15.f);
    float e = __expf(-2.f * x);
    return __fdividef(1.f - e, 1.f + e);
}

// stage one 8x128 W chunk (warp-private slice) via cp.async
__device__ __forceinline__ void stage_chunk(float* wbuf, int kc, int wp, int ln) {
#pragma unroll
    for (int it = 0; it < 8; ++it) {
        cp_async16(wbuf + it * WB_LD + ln * 4,
                   &g_WhhT[(size_t)(kc * 8 + it) * 1024 + wp * 128 + ln * 4]);
    }
}

// ---------------- main persistent LSTM kernel ----------------
__global__ void __launch_bounds__(256, 1)
lstm_kernel(const float* __restrict__ w,
            const float* __restrict__ W_out,
            const float* __restrict__ b_out,
            float* __restrict__ out) {
    extern __shared__ float sm[];
    float* h_tf   = sm + OFF_H;     // tf32-rounded h (mma operand)
    float* h_ex   = sm + OFF_HE;    // exact fp32 h (for head / output)
    float* x_sm   = sm + OFF_X;
    float* bias_sm= sm + OFF_BIAS;
    float* wout_sm= sm + OFF_WOUT;
    float* wih_sm = sm + OFF_WIH;   // [16][W_LD]
    float* shreg  = sm + OFF_SH;    // per-warp W dbl-buffers / gate scratch (aliased)

    const int tid = threadIdx.x;
    const int wp  = tid >> 5;
    const int ln  = tid & 31;
    const int b0  = blockIdx.x * MT;

    // init
    for (int i = tid; i < MT * LDH; i += 256) { h_tf[i] = 0.f; h_ex[i] = 0.f; }
    for (int i = tid; i < 1024; i += 256) bias_sm[i] = g_biasP[i];
    for (int i = tid; i < 512; i += 256) wout_sm[i] = W_out[i];
    if (tid < 2) wout_sm[512 + tid] = b_out[tid];
    for (int i = tid; i < 16 * 1024; i += 256) {
        int k = i >> 10, n = i & 1023;
        wih_sm[k * W_LD + n] = g_WihT[i];
    }
    __syncthreads();

    // warp wp owns: all 32 rows x perm cols [wp*128, wp*128+128) = hidden units [wp*32, wp*32+32)
    const int phase = wp >> 2;           // each phase: 4 warps on 4 distinct SMSPs
    const int slot  = wp & 3;
    float* scr   = shreg + slot * 4224;  // 32 x SCR_LD
    float* wbuf0 = shreg + wp * 2112;    // 8 x WB_LD
    float* wbuf1 = wbuf0 + 1056;

    // cell state: lane owns 8 rows x 4 units = 32 cells
    float creg[32];
#pragma unroll
    for (int i = 0; i < 32; i++) creg[i] = 0.f;

    wmma::fragment<wmma::accumulator, 16, 16, 8, float> acc0[8], acc1[8];

    const int rbase = (ln >> 3) * 8;
    const int ub    = ln & 7;

    for (int t = 0; t < TSTEPS; ++t) {
        // stage x_t (tf32-rounded)
        for (int i = tid; i < MT * FDIM; i += 256) {
            int r = i >> 4, f = i & 15;
            x_sm[r * X_LD + f] =
                wmma::__float_to_tf32(w[((size_t)(b0 + r) * TSTEPS + t) * FDIM + f]);
        }
        __syncthreads();  // B0: x ready, prev-step h/scratch consumers done

        // prefetch W chunk 0 (warp-private)
        stage_chunk(wbuf0, 0, wp, ln);
        cp_commit();

#pragma unroll
        for (int i = 0; i < 8; i++) { wmma::fill_fragment(acc0[i], 0.f); wmma::fill_fragment(acc1[i], 0.f); }

        // x @ W_ih^T : K=16 (2 k-steps), overlaps chunk-0 cp.async
#pragma unroll
        for (int ks = 0; ks < 2; ++ks) {
            wmma::fragment<wmma::matrix_a, 16, 16, 8, wmma::precision::tf32, wmma::row_major> a0, a1;
            wmma::load_matrix_sync(a0, x_sm + ks * 8, X_LD);
            wmma::load_matrix_sync(a1, x_sm + 16 * X_LD + ks * 8, X_LD);
#pragma unroll
            for (int i = 0; i < 8; i++) {
                wmma::fragment<wmma::matrix_b, 16, 16, 8, wmma::precision::tf32, wmma::row_major> bf;
                wmma::load_matrix_sync(bf, wih_sm + ks * 8 * W_LD + wp * 128 + i * 16, W_LD);
                wmma::mma_sync(acc0[i], a0, bf, acc0[i]);
                wmma::mma_sync(acc1[i], a1, bf, acc1[i]);
            }
        }

        // h @ W_hh^T : K=256, 32 chunks, warp-private double buffer, NO barriers
        for (int kc = 0; kc < 32; ++kc) {
            float* cur = (kc & 1) ? wbuf1 : wbuf0;
            if (kc < 31) {
                stage_chunk((kc & 1) ? wbuf0 : wbuf1, kc + 1, wp, ln);
                cp_commit();
                cp_wait1();          // current chunk's group complete
            } else {
                cp_wait0();
            }
            __syncwarp();
            wmma::fragment<wmma::matrix_a, 16, 16, 8, wmma::precision::tf32, wmma::row_major> a0, a1;
            wmma::load_matrix_sync(a0, h_tf + kc * 8, LDH);
            wmma::load_matrix_sync(a1, h_tf + 16 * LDH + kc * 8, LDH);
#pragma unroll
            for (int i = 0; i < 8; i++) {
                wmma::fragment<wmma::matrix_b, 16, 16, 8, wmma::precision::tf32, wmma::row_major> bf;
                wmma::load_matrix_sync(bf, cur + i * 16, WB_LD);
                wmma::mma_sync(acc0[i], a0, bf, acc0[i]);
                wmma::mma_sync(acc1[i], a1, bf, acc1[i]);
            }
        }
        __syncthreads();  // B1: all mma done before scratch overwrites W buffers

        // epilogue: 2 phases x 4 warps (one per SMSP each phase)
#pragma unroll
        for (int ph = 0; ph < 2; ++ph) {
            if (phase == ph) {
#pragma unroll
                for (int i = 0; i < 8; i++) {
                    wmma::store_matrix_sync(scr + i * 16, acc0[i], SCR_LD, wmma::mem_row_major);
                    wmma::store_matrix_sync(scr + 16 * SCR_LD + i * 16, acc1[i], SCR_LD, wmma::mem_row_major);
                }
                __syncwarp();
                float4 bv[4];
#pragma unroll
                for (int uu = 0; uu < 4; ++uu)
                    bv[uu] = *reinterpret_cast<const float4*>(bias_sm + (wp * 32 + ub + uu * 8) * 4);
#pragma unroll
                for (int rr = 0; rr < 8; ++rr) {
                    const int r = rbase + rr;
#pragma unroll
                    for (int uu = 0; uu < 4; ++uu) {
                        const int ul = ub + uu * 8;
                        float4 gv = *reinterpret_cast<float4*>(scr + r * SCR_LD + ul * 4);
                        float gi = sig_approx(gv.x + bv[uu].x);
                        float gf = sig_approx(gv.y + bv[uu].y);
                        float gg = tanhf_fast(gv.z + bv[uu].z);
                        float go = sig_approx(gv.w + bv[uu].w);
                        const int ci = rr * 4 + uu;
                        float c = gf * creg[ci] + gi * gg;
                        creg[ci] = c;
                        float hn = go * tanhf_fast(c);
                        const int jg = wp * 32 + ul;
                        h_ex[r * LDH + jg] = hn;
                        h_tf[r * LDH + jg] = wmma::__float_to_tf32(hn);
                        if (t == TSTEPS - 1)
                            out[8192 + (size_t)(b0 + r) * 256 + jg] = hn;
                    }
                }
            }
            __syncthreads();  // B2 / B3
        }
    }

    // head: tz0 = ELU(h) @ W_out^T + b_out  (exact fp32)
    if (tid < 64) {
        const int r = tid >> 1, oi = tid & 1;
        float s = wout_sm[512 + oi];
        for (int j = 0; j < 256; ++j) {
            float v = h_ex[r * LDH + j];
            float e = (v > 0.f) ? v : (__expf(v) - 1.f);
            s += e * wout_sm[oi * 256 + j];
        }
        out[(size_t)oi * 4096 + (b0 + r)] = s;
    }
}

// ---------------- launch ----------------
extern "C" void kernel_launch(void* const* d_in, const int* in_sizes, int n_in,
                              void* d_out, int out_size) {
    const float* w     = (const float*)d_in[0];
    const float* W_ih  = (const float*)d_in[1];
    const float* W_hh  = (const float*)d_in[2];
    const float* b_ih  = (const float*)d_in[3];
    const float* b_hh  = (const float*)d_in[4];
    const float* W_out = (const float*)d_in[5];
    const float* b_out = (const float*)d_in[6];
    float* out = (float*)d_out;

    prep_kernel<<<256, 256>>>(W_ih, W_hh, b_ih, b_hh);

    const int smem_bytes = SMEM_FLOATS * sizeof(float);  // 210944 B
    cudaFuncSetAttribute(lstm_kernel, cudaFuncAttributeMaxDynamicSharedMemorySize, smem_bytes);
    lstm_kernel<<<NCTA, 256, smem_bytes>>>(w, W_out, b_out, out);
}